// round 7
// baseline (speedup 1.0000x reference)
#include <cuda_runtime.h>
#include <cuda_bf16.h>
#include <cmath>

#define B_ 32
#define N_ 16384
#define D_ 64
#define S_ 8
#define H_ 128
#define LNEPS 1e-5f
#define ATTN_EPS 1e-8f

typedef unsigned long long ull;

// ---------------- scratch (device globals; no allocations allowed) ----------
__device__ unsigned g_kh[B_ * N_ * 32];   // k_pos as bf16x2 pairs (64 MB)
__device__ unsigned g_vh[B_ * N_ * 32];   // v_pos as bf16x2 pairs (64 MB)
__device__ float g_q[B_ * S_ * D_];
__device__ float g_s[B_ * S_ * D_];
__device__ float g_part[B_ * 64 * 520];   // per-(b, partial-block) numer(512)+den(8)

// ---------------- f32x2 helpers ---------------------------------------------
__device__ __forceinline__ ull pk2(float x, float y) {
    ull r; asm("mov.b64 %0,{%1,%2};" : "=l"(r) : "f"(x), "f"(y)); return r;
}
__device__ __forceinline__ void up2(ull v, float& x, float& y) {
    asm("mov.b64 {%0,%1},%2;" : "=f"(x), "=f"(y) : "l"(v));
}
__device__ __forceinline__ void fma2(ull& d, ull a, ull b) {
    asm("fma.rn.f32x2 %0,%1,%2,%0;" : "+l"(d) : "l"(a), "l"(b));
}
__device__ __forceinline__ unsigned bf2u(float a, float b) {
    __nv_bfloat162 h = __float22bfloat162_rn(make_float2(a, b));
    return *(unsigned*)&h;
}
__device__ __forceinline__ float2 u2f2(unsigned u) {
    __nv_bfloat162 h = *(__nv_bfloat162*)&u;
    return __bfloat1622float2(h);
}

// ---------------------------------------------------------------------------
// Kernel 1: fused preprocessing, 64-row tiles, f32x2 GEMMs.
// smem float offsets:
//   sWk 0, sWv 4096, sW1 8192, sW2 16384, sV 24576 (640),
//   sX 25216 (64x64), sG 29312 (128), sTk 29440, sTv 33536,
//   sH 37632 (64x132)  -> total 46080 floats = 184320 B
// ---------------------------------------------------------------------------
#define PRE_SMEM_FLOATS 46080

__global__ __launch_bounds__(256, 1) void preprocess_kernel(
    const float* __restrict__ inp,
    const float* __restrict__ lng, const float* __restrict__ lnb,
    const float* __restrict__ Wk,  const float* __restrict__ Wv,
    const float* __restrict__ paW, const float* __restrict__ pab,
    const float* __restrict__ peg, const float* __restrict__ peb,
    const float* __restrict__ W1,  const float* __restrict__ b1,
    const float* __restrict__ W2,  const float* __restrict__ b2)
{
    extern __shared__ float smem[];
    float* sWk = smem;
    float* sWv = smem + 4096;
    float* sW1 = smem + 8192;
    float* sW2 = smem + 16384;
    float* sV  = smem + 24576;
    float* sX  = smem + 25216;
    float* sG  = smem + 29312;
    float* sTk = smem + 29440;
    float* sTv = smem + 33536;
    float* sH  = smem + 37632;   // stride 132

    const int t = threadIdx.x, warp = t >> 5, lane = t & 31;

    for (int i = t; i < 4096; i += 256) { sWk[i] = Wk[i]; sWv[i] = Wv[i]; }
    for (int i = t; i < 8192; i += 256) { sW1[i] = W1[i]; sW2[i] = W2[i]; }
    if (t < 64) {
        sV[t]       = paW[t];
        sV[64 + t]  = paW[64 + t];
        sV[128 + t] = pab[t];
        sV[192 + t] = lng[t];
        sV[256 + t] = lnb[t];
        sV[320 + t] = peg[t];
        sV[384 + t] = peb[t];
        sV[576 + t] = b2[t];
    }
    if (t < 128) sV[448 + t] = b1[t];
    __syncthreads();

    const float *pa0 = sV, *pa1 = sV + 64, *pbv = sV + 128,
                *sing = sV + 192, *sinb = sV + 256,
                *speg = sV + 320, *speb = sV + 384,
                *sb1 = sV + 448, *sb2 = sV + 576;

    const int c0 = lane * 2;
    const int c4 = lane * 4;

    for (int ti = 0; ti < 4; ti++) {
        int tile = blockIdx.x * 4 + ti;          // 8192 tiles of 64 rows
        int rowbase = tile * 64;

        // ---- LN of input features (warp-per-row) + grids ----
        for (int rr = warp; rr < 64; rr += 8) {
            const float* rp = inp + (size_t)(rowbase + rr) * 66;
            float x0 = rp[lane], x1 = rp[lane + 32];
            float s1 = x0 + x1, s2 = x0 * x0 + x1 * x1;
            #pragma unroll
            for (int o = 16; o; o >>= 1) {
                s1 += __shfl_xor_sync(0xffffffffu, s1, o);
                s2 += __shfl_xor_sync(0xffffffffu, s2, o);
            }
            float mu = s1 * 0.015625f;
            float var = s2 * 0.015625f - mu * mu;
            float rs = rsqrtf(var + LNEPS);
            sX[rr * 64 + lane]      = (x0 - mu) * rs * sing[lane]      + sinb[lane];
            sX[rr * 64 + lane + 32] = (x1 - mu) * rs * sing[lane + 32] + sinb[lane + 32];
            if (lane < 2) sG[rr * 2 + lane] = rp[64 + lane];
        }
        __syncthreads();

        // ---- fused GEMM1: T_k = X@Wk + gp, T_v = X@Wv + gp ----
        {
            ull ak[8], av[8];
            #pragma unroll
            for (int j = 0; j < 8; j++) { ak[j] = 0ull; av[j] = 0ull; }
            const float* xs = sX + warp * 8 * 64;
            #pragma unroll 4
            for (int k = 0; k < 64; k++) {
                ull wk = *(const ull*)(sWk + k * 64 + c0);
                ull wv = *(const ull*)(sWv + k * 64 + c0);
                #pragma unroll
                for (int j = 0; j < 8; j++) {
                    float a = xs[j * 64 + k];
                    ull aa = pk2(a, a);
                    fma2(ak[j], aa, wk);
                    fma2(av[j], aa, wv);
                }
            }
            float p0 = pa0[c0], p0b = pa0[c0 + 1];
            float p1 = pa1[c0], p1b = pa1[c0 + 1];
            float pb_ = pbv[c0], pbb = pbv[c0 + 1];
            #pragma unroll
            for (int j = 0; j < 8; j++) {
                int r = warp * 8 + j;
                float gx = sG[r * 2], gy = sG[r * 2 + 1];
                float g0 = gx * p0 + gy * p1 + pb_;
                float g1 = gx * p0b + gy * p1b + pbb;
                float k0, k1, v0, v1;
                up2(ak[j], k0, k1); up2(av[j], v0, v1);
                sTk[r * 64 + c0]     = k0 + g0;
                sTk[r * 64 + c0 + 1] = k1 + g1;
                sTv[r * 64 + c0]     = v0 + g0;
                sTv[r * 64 + c0 + 1] = v1 + g1;
            }
        }
        __syncthreads();

        // ---- LN (pe) on both T tiles, in place ----
        for (int rr = warp; rr < 64; rr += 8) {
            #pragma unroll
            for (int which = 0; which < 2; which++) {
                float* T = which ? sTv : sTk;
                float x0 = T[rr * 64 + lane], x1 = T[rr * 64 + lane + 32];
                float s1 = x0 + x1, s2 = x0 * x0 + x1 * x1;
                #pragma unroll
                for (int o = 16; o; o >>= 1) {
                    s1 += __shfl_xor_sync(0xffffffffu, s1, o);
                    s2 += __shfl_xor_sync(0xffffffffu, s2, o);
                }
                float mu = s1 * 0.015625f;
                float var = s2 * 0.015625f - mu * mu;
                float rs = rsqrtf(var + LNEPS);
                T[rr * 64 + lane]      = (x0 - mu) * rs * speg[lane]      + speb[lane];
                T[rr * 64 + lane + 32] = (x1 - mu) * rs * speg[lane + 32] + speb[lane + 32];
            }
        }
        __syncthreads();

        #pragma unroll 1
        for (int pass = 0; pass < 2; pass++) {
            const float* T = pass ? sTv : sTk;
            unsigned* outg = pass ? g_vh : g_kh;

            // ---- GEMM2: H = relu(T @ pe_W1 + b1) ----
            {
                ull acc[8][2];
                #pragma unroll
                for (int j = 0; j < 8; j++) { acc[j][0] = 0ull; acc[j][1] = 0ull; }
                const float* tb = T + warp * 8 * 64;
                #pragma unroll 4
                for (int k = 0; k < 64; k++) {
                    ulonglong2 w = *(const ulonglong2*)(sW1 + k * 128 + c4);
                    #pragma unroll
                    for (int j = 0; j < 8; j++) {
                        float a = tb[j * 64 + k];
                        ull aa = pk2(a, a);
                        fma2(acc[j][0], aa, w.x);
                        fma2(acc[j][1], aa, w.y);
                    }
                }
                float4 bb = *(const float4*)(sb1 + c4);
                #pragma unroll
                for (int j = 0; j < 8; j++) {
                    int r = warp * 8 + j;
                    float h0, h1, h2, h3;
                    up2(acc[j][0], h0, h1); up2(acc[j][1], h2, h3);
                    float4 o;
                    o.x = fmaxf(h0 + bb.x, 0.f);
                    o.y = fmaxf(h1 + bb.y, 0.f);
                    o.z = fmaxf(h2 + bb.z, 0.f);
                    o.w = fmaxf(h3 + bb.w, 0.f);
                    *(float4*)(sH + r * 132 + c4) = o;
                }
            }
            __syncthreads();

            // ---- GEMM3: out = H @ pe_W2 + b2  -> bf16x2 gmem ----
            {
                int g = lane >> 4, cl = (lane & 15) * 4;
                ull acc[4][2];
                #pragma unroll
                for (int jj = 0; jj < 4; jj++) { acc[jj][0] = 0ull; acc[jj][1] = 0ull; }
                const float* hb = sH + (warp * 8 + g * 4) * 132;
                #pragma unroll 4
                for (int k = 0; k < 128; k++) {
                    ulonglong2 w = *(const ulonglong2*)(sW2 + k * 64 + cl);
                    #pragma unroll
                    for (int jj = 0; jj < 4; jj++) {
                        float a = hb[jj * 132 + k];
                        ull aa = pk2(a, a);
                        fma2(acc[jj][0], aa, w.x);
                        fma2(acc[jj][1], aa, w.y);
                    }
                }
                float b0 = sb2[cl], b1_ = sb2[cl + 1], b2_ = sb2[cl + 2], b3 = sb2[cl + 3];
                #pragma unroll
                for (int jj = 0; jj < 4; jj++) {
                    int r = warp * 8 + g * 4 + jj;
                    float o0, o1, o2, o3;
                    up2(acc[jj][0], o0, o1); up2(acc[jj][1], o2, o3);
                    uint2 pkd;
                    pkd.x = bf2u(o0 + b0, o1 + b1_);
                    pkd.y = bf2u(o2 + b2_, o3 + b3);
                    *(uint2*)(outg + (size_t)(rowbase + r) * 32 + (cl >> 1)) = pkd;
                }
            }
            __syncthreads();
        }
    }
}

// ---------------------------------------------------------------------------
// Kernel 2: init slot state
// ---------------------------------------------------------------------------
__global__ void init_slots_kernel(const float* __restrict__ slots)
{
    g_s[blockIdx.x * 512 + threadIdx.x] = slots[threadIdx.x];
}

// ---------------------------------------------------------------------------
// Kernel 3: q = LN(s; ln_s) @ Wq  (one block per b)
// ---------------------------------------------------------------------------
__global__ __launch_bounds__(256) void slotq_kernel(
    const float* __restrict__ lnsg, const float* __restrict__ lnsb,
    const float* __restrict__ Wq)
{
    __shared__ float sln[512];
    int b = blockIdx.x, t = threadIdx.x, warp = t >> 5, lane = t & 31;
    {
        const float* row = g_s + b * 512 + warp * 64;
        float x0 = row[lane], x1 = row[lane + 32];
        float s1 = x0 + x1, s2 = x0 * x0 + x1 * x1;
        #pragma unroll
        for (int o = 16; o; o >>= 1) {
            s1 += __shfl_xor_sync(0xffffffffu, s1, o);
            s2 += __shfl_xor_sync(0xffffffffu, s2, o);
        }
        float mu = s1 * 0.015625f;
        float var = s2 * 0.015625f - mu * mu;
        float rs = rsqrtf(var + LNEPS);
        sln[warp * 64 + lane]      = (x0 - mu) * rs * lnsg[lane]      + lnsb[lane];
        sln[warp * 64 + lane + 32] = (x1 - mu) * rs * lnsg[lane + 32] + lnsb[lane + 32];
    }
    __syncthreads();
    for (int i = t; i < 512; i += 256) {
        int s = i >> 6, c = i & 63;
        float a = 0.f;
        #pragma unroll 8
        for (int d = 0; d < 64; d++) a += sln[s * 64 + d] * Wq[d * 64 + c];
        g_q[b * 512 + i] = a;
    }
}

// ---------------------------------------------------------------------------
// Kernel 4: attention, shuffle-free. Grid = B*64 blocks, 256 thr (8 warps).
// Each warp handles 32 rows; each lane owns one row for logits+softmax, then
// lanes own 2 d-columns for the a^T @ v accumulation.
// dyn smem floats: qT 0(512) | sK 512 (8*32*65) | sA 17152 (8*256) |
//                  wacc 19200 (8*520)  -> total 23360 floats = 93440 B
// ---------------------------------------------------------------------------
#define ATTN_SMEM_FLOATS 23360

__global__ __launch_bounds__(256) void attn_kernel()
{
    extern __shared__ float sm[];
    float* qT   = sm;                  // [64][8]
    float* sKb  = sm + 512;            // per-warp [32][65]
    float* sAb  = sm + 17152;          // per-warp [32][8]
    float* wacc = sm + 19200;          // [8][520]

    int b = blockIdx.x >> 6, pb = blockIdx.x & 63;
    int t = threadIdx.x, warp = t >> 5, lane = t & 31;

    for (int i = t; i < 512; i += 256) {
        int s = i >> 6, d = i & 63;
        qT[d * 8 + s] = g_q[b * 512 + i];
    }
    __syncthreads();

    size_t rowbase = (size_t)b * N_ + pb * 256 + warp * 32;
    const unsigned* kp = g_kh + rowbase * 32;
    const unsigned* vp = g_vh + rowbase * 32;

    // ---- stage k tile to fp32 smem (stride 65, conflict-free reads) ----
    float* mk = sKb + warp * 2080;
    #pragma unroll 4
    for (int i = 0; i < 32; i++) {
        float2 f = u2f2(kp[i * 32 + lane]);
        mk[i * 65 + lane * 2]     = f.x;
        mk[i * 65 + lane * 2 + 1] = f.y;
    }
    __syncwarp();

    // ---- logits for own row (row = lane) ----
    float lg[8];
    #pragma unroll
    for (int s = 0; s < 8; s++) lg[s] = 0.f;
    {
        const float* myk = mk + lane * 65;
        #pragma unroll 8
        for (int d = 0; d < 64; d++) {
            float kd = myk[d];
            float4 qa = *(const float4*)(qT + d * 8);
            float4 qb = *(const float4*)(qT + d * 8 + 4);
            lg[0] += kd * qa.x; lg[1] += kd * qa.y;
            lg[2] += kd * qa.z; lg[3] += kd * qa.w;
            lg[4] += kd * qb.x; lg[5] += kd * qb.y;
            lg[6] += kd * qb.z; lg[7] += kd * qb.w;
        }
    }
    // ---- per-lane softmax over S=8, + eps ----
    float den8[8];
    {
        #pragma unroll
        for (int s = 0; s < 8; s++) lg[s] *= 0.125f;
        float mx = lg[0];
        #pragma unroll
        for (int s = 1; s < 8; s++) mx = fmaxf(mx, lg[s]);
        float se = 0.f;
        #pragma unroll
        for (int s = 0; s < 8; s++) { lg[s] = __expf(lg[s] - mx); se += lg[s]; }
        float inv = 1.f / se;
        #pragma unroll
        for (int s = 0; s < 8; s++) { lg[s] = lg[s] * inv + ATTN_EPS; den8[s] = lg[s]; }
        float* pa = sAb + warp * 256 + lane * 8;
        float4 w0 = make_float4(lg[0], lg[1], lg[2], lg[3]);
        float4 w1 = make_float4(lg[4], lg[5], lg[6], lg[7]);
        *(float4*)pa = w0;
        *(float4*)(pa + 4) = w1;
    }
    __syncwarp();

    // ---- accumulate numer[s][2 cols per lane] over the 32 rows ----
    float acc0[8], acc1[8];
    #pragma unroll
    for (int s = 0; s < 8; s++) { acc0[s] = 0.f; acc1[s] = 0.f; }
    {
        const float* pa = sAb + warp * 256;
        #pragma unroll 4
        for (int i = 0; i < 32; i++) {
            float2 v = u2f2(vp[i * 32 + lane]);
            float4 a0 = *(const float4*)(pa + i * 8);
            float4 a1 = *(const float4*)(pa + i * 8 + 4);
            acc0[0] += a0.x * v.x; acc1[0] += a0.x * v.y;
            acc0[1] += a0.y * v.x; acc1[1] += a0.y * v.y;
            acc0[2] += a0.z * v.x; acc1[2] += a0.z * v.y;
            acc0[3] += a0.w * v.x; acc1[3] += a0.w * v.y;
            acc0[4] += a1.x * v.x; acc1[4] += a1.x * v.y;
            acc0[5] += a1.y * v.x; acc1[5] += a1.y * v.y;
            acc0[6] += a1.z * v.x; acc1[6] += a1.z * v.y;
            acc0[7] += a1.w * v.x; acc1[7] += a1.w * v.y;
        }
    }
    // ---- reduce den across lanes (once per tile) ----
    #pragma unroll
    for (int s = 0; s < 8; s++) {
        float d = den8[s];
        #pragma unroll
        for (int o = 16; o; o >>= 1) d += __shfl_xor_sync(0xffffffffu, d, o);
        den8[s] = d;
    }

    float* wa = wacc + warp * 520;
    #pragma unroll
    for (int s = 0; s < 8; s++) {
        wa[s * 64 + lane * 2]     = acc0[s];
        wa[s * 64 + lane * 2 + 1] = acc1[s];
    }
    if (lane == 0) {
        #pragma unroll
        for (int s = 0; s < 8; s++) wa[512 + s] = den8[s];
    }
    __syncthreads();

    float* dst = g_part + (size_t)blockIdx.x * 520;
    for (int i = t; i < 520; i += 256) {
        float v = 0.f;
        #pragma unroll
        for (int w = 0; w < 8; w++) v += wacc[w * 520 + i];
        dst[i] = v;
    }
}

// ---------------------------------------------------------------------------
// Kernel 5: reduce partials -> updates -> GRU -> MLP residual (one block/b)
// ---------------------------------------------------------------------------
__global__ __launch_bounds__(256) void update_kernel(
    const float* __restrict__ W_ih, const float* __restrict__ W_hh,
    const float* __restrict__ b_ih, const float* __restrict__ b_hh,
    const float* __restrict__ lnmg, const float* __restrict__ lnmb,
    const float* __restrict__ mW1,  const float* __restrict__ mb1,
    const float* __restrict__ mW2,  const float* __restrict__ mb2,
    float* __restrict__ dout)
{
    __shared__ float red[520];
    __shared__ float u[512], prev[512], gx[1536], gh[1536];
    __shared__ float snew[512], sln[512], h1[1024];
    int b = blockIdx.x, t = threadIdx.x, warp = t >> 5, lane = t & 31;

    for (int i = t; i < 520; i += 256) {
        float v = 0.f;
        const float* p = g_part + (size_t)(b * 64) * 520 + i;
        #pragma unroll 8
        for (int pp = 0; pp < 64; pp++) v += p[pp * 520];
        red[i] = v;
    }
    for (int i = t; i < 512; i += 256) prev[i] = g_s[b * 512 + i];
    __syncthreads();

    for (int i = t; i < 512; i += 256) u[i] = red[i] / red[512 + (i >> 6)];
    __syncthreads();

    for (int i = t; i < 1536; i += 256) {
        int s = i / 192, j = i - s * 192;
        float ax = b_ih[j], ah = b_hh[j];
        const float* us = u + s * 64;
        const float* ps = prev + s * 64;
        #pragma unroll 8
        for (int d = 0; d < 64; d++) {
            ax += us[d] * W_ih[d * 192 + j];
            ah += ps[d] * W_hh[d * 192 + j];
        }
        gx[i] = ax; gh[i] = ah;
    }
    __syncthreads();

    for (int i = t; i < 512; i += 256) {
        int s = i >> 6, dd = i & 63;
        float xr = gx[s * 192 + dd], xz = gx[s * 192 + 64 + dd], xn = gx[s * 192 + 128 + dd];
        float hr = gh[s * 192 + dd], hz = gh[s * 192 + 64 + dd], hn = gh[s * 192 + 128 + dd];
        float r_ = 1.f / (1.f + __expf(-(xr + hr)));
        float z  = 1.f / (1.f + __expf(-(xz + hz)));
        float nn = tanhf(xn + r_ * hn);
        snew[i] = (1.f - z) * nn + z * prev[i];
    }
    __syncthreads();

    {
        const float* row = snew + warp * 64;
        float x0 = row[lane], x1 = row[lane + 32];
        float s1 = x0 + x1, s2 = x0 * x0 + x1 * x1;
        #pragma unroll
        for (int o = 16; o; o >>= 1) {
            s1 += __shfl_xor_sync(0xffffffffu, s1, o);
            s2 += __shfl_xor_sync(0xffffffffu, s2, o);
        }
        float mu = s1 * 0.015625f;
        float var = s2 * 0.015625f - mu * mu;
        float rs = rsqrtf(var + LNEPS);
        sln[warp * 64 + lane]      = (x0 - mu) * rs * lnmg[lane]      + lnmb[lane];
        sln[warp * 64 + lane + 32] = (x1 - mu) * rs * lnmg[lane + 32] + lnmb[lane + 32];
    }
    __syncthreads();

    for (int i = t; i < 1024; i += 256) {
        int s = i >> 7, j = i & 127;
        float a = mb1[j];
        const float* r = sln + s * 64;
        #pragma unroll 8
        for (int d = 0; d < 64; d++) a += r[d] * mW1[d * 128 + j];
        h1[i] = fmaxf(a, 0.f);
    }
    __syncthreads();

    for (int i = t; i < 512; i += 256) {
        int s = i >> 6, c = i & 63;
        float a = mb2[c];
        const float* r = h1 + s * 128;
        #pragma unroll 8
        for (int k = 0; k < 128; k++) a += r[k] * mW2[k * 64 + c];
        float val = snew[i] + a;
        g_s[b * 512 + i] = val;
        dout[b * 512 + i] = val;
    }
}

// ---------------------------------------------------------------------------
extern "C" void kernel_launch(void* const* d_in, const int* in_sizes, int n_in,
                              void* d_out, int out_size)
{
    (void)in_sizes; (void)n_in; (void)out_size;
    const float* inputs  = (const float*)d_in[0];
    const float* slots   = (const float*)d_in[1];
    const float* ln_in_g = (const float*)d_in[2];
    const float* ln_in_b = (const float*)d_in[3];
    const float* ln_s_g  = (const float*)d_in[4];
    const float* ln_s_b  = (const float*)d_in[5];
    const float* ln_m_g  = (const float*)d_in[6];
    const float* ln_m_b  = (const float*)d_in[7];
    const float* Wq      = (const float*)d_in[8];
    const float* Wk      = (const float*)d_in[9];
    const float* Wv      = (const float*)d_in[10];
    const float* W_ih    = (const float*)d_in[11];
    const float* W_hh    = (const float*)d_in[12];
    const float* b_ih    = (const float*)d_in[13];
    const float* b_hh    = (const float*)d_in[14];
    const float* mlp_W1  = (const float*)d_in[15];
    const float* mlp_b1  = (const float*)d_in[16];
    const float* mlp_W2  = (const float*)d_in[17];
    const float* mlp_b2  = (const float*)d_in[18];
    const float* pa_W    = (const float*)d_in[19];
    const float* pa_b    = (const float*)d_in[20];
    const float* pe_g    = (const float*)d_in[21];
    const float* pe_b    = (const float*)d_in[22];
    const float* pe_W1   = (const float*)d_in[23];
    const float* pe_b1   = (const float*)d_in[24];
    const float* pe_W2   = (const float*)d_in[25];
    const float* pe_b2   = (const float*)d_in[26];
    float* out = (float*)d_out;

    static int configured = 0;
    const int pre_smem = PRE_SMEM_FLOATS * 4;
    const int attn_smem = ATTN_SMEM_FLOATS * 4;
    if (!configured) {
        cudaFuncSetAttribute(preprocess_kernel,
                             cudaFuncAttributeMaxDynamicSharedMemorySize, pre_smem);
        cudaFuncSetAttribute(attn_kernel,
                             cudaFuncAttributeMaxDynamicSharedMemorySize, attn_smem);
        configured = 1;
    }

    preprocess_kernel<<<2048, 256, pre_smem>>>(
        inputs, ln_in_g, ln_in_b, Wk, Wv, pa_W, pa_b, pe_g, pe_b,
        pe_W1, pe_b1, pe_W2, pe_b2);

    init_slots_kernel<<<32, 512>>>(slots);

    for (int it = 0; it < 3; it++) {
        slotq_kernel<<<32, 256>>>(ln_s_g, ln_s_b, Wq);
        attn_kernel<<<2048, 256, attn_smem>>>();
        update_kernel<<<32, 256>>>(W_ih, W_hh, b_ih, b_hh,
                                   ln_m_g, ln_m_b,
                                   mlp_W1, mlp_b1, mlp_W2, mlp_b2, out);
    }
}

// round 8
// speedup vs baseline: 1.6371x; 1.6371x over previous
#include <cuda_runtime.h>
#include <cuda_bf16.h>
#include <cmath>

#define B_ 32
#define N_ 16384
#define D_ 64
#define S_ 8
#define H_ 128
#define LNEPS 1e-5f
#define ATTN_EPS 1e-8f

typedef unsigned long long ull;
typedef unsigned int u32;

// ---------------- scratch (device globals; no allocations allowed) ----------
__device__ unsigned g_kh[B_ * N_ * 32];   // k_pos as bf16x2 pairs (64 MB)
__device__ unsigned g_vh[B_ * N_ * 32];   // v_pos as bf16x2 pairs (64 MB)
__device__ float g_q[B_ * S_ * D_];
__device__ float g_s[B_ * S_ * D_];
__device__ float g_part[B_ * 64 * 520];   // per-(b, partial-block) numer(512)+den(8)

// ---------------- helpers ----------------------------------------------------
__device__ __forceinline__ unsigned bf2u(float a, float b) {
    __nv_bfloat162 h = __float22bfloat162_rn(make_float2(a, b));
    return *(unsigned*)&h;
}
__device__ __forceinline__ float2 u2f2(unsigned u) {
    __nv_bfloat162 h = *(__nv_bfloat162*)&u;
    return __bfloat1622float2(h);
}
__device__ __forceinline__ void ldsm_x4(u32 a[4], u32 addr) {
    asm volatile("ldmatrix.sync.aligned.m8n8.x4.shared.b16 {%0,%1,%2,%3}, [%4];"
                 : "=r"(a[0]), "=r"(a[1]), "=r"(a[2]), "=r"(a[3]) : "r"(addr));
}
__device__ __forceinline__ void ldsm_x2t(u32 b[2], u32 addr) {
    asm volatile("ldmatrix.sync.aligned.m8n8.x2.trans.shared.b16 {%0,%1}, [%2];"
                 : "=r"(b[0]), "=r"(b[1]) : "r"(addr));
}
__device__ __forceinline__ void mma_bf16(float d[4], const u32 a[4], const u32 b[2]) {
    asm volatile("mma.sync.aligned.m16n8k16.row.col.f32.bf16.bf16.f32 "
                 "{%0,%1,%2,%3},{%4,%5,%6,%7},{%8,%9},{%0,%1,%2,%3};"
                 : "+f"(d[0]), "+f"(d[1]), "+f"(d[2]), "+f"(d[3])
                 : "r"(a[0]), "r"(a[1]), "r"(a[2]), "r"(a[3]), "r"(b[0]), "r"(b[1]));
}

// ---------------------------------------------------------------------------
// Kernel 1: fused preprocessing with bf16 tensor-core GEMMs. 64-row tiles.
// smem byte layout (16B aligned blocks):
//   Wk_b   @      0 : 64x72  bf16 =  9216
//   Wv_b   @   9216 : 64x72  bf16 =  9216
//   W1_b   @  18432 : 64x136 bf16 = 17408
//   W2_b   @  35840 : 128x72 bf16 = 18432
//   X_b    @  54272 : 64x72  bf16 =  9216
//   Tk_f   @  63488 : 64x66  f32  = 16896
//   Tv_f   @  80384 : 64x66  f32  = 16896
//   Tk_b   @  97280 : 64x72  bf16 =  9216
//   Tv_b   @ 106496 : 64x72  bf16 =  9216
//   H_b    @ 115712 : 64x136 bf16 = 17408
//   V_f    @ 133120 : 640 f32     =  2560
//   G_f    @ 135680 : 128 f32     =   512   -> total 136192 B
// ---------------------------------------------------------------------------
#define PRE_SMEM_BYTES 136192

__global__ __launch_bounds__(256, 1) void preprocess_kernel(
    const float* __restrict__ inp,
    const float* __restrict__ lng, const float* __restrict__ lnb,
    const float* __restrict__ Wk,  const float* __restrict__ Wv,
    const float* __restrict__ paW, const float* __restrict__ pab,
    const float* __restrict__ peg, const float* __restrict__ peb,
    const float* __restrict__ W1,  const float* __restrict__ b1,
    const float* __restrict__ W2,  const float* __restrict__ b2)
{
    extern __shared__ char smem[];
    __nv_bfloat16* sWk = (__nv_bfloat16*)(smem);
    __nv_bfloat16* sWv = (__nv_bfloat16*)(smem + 9216);
    __nv_bfloat16* sW1 = (__nv_bfloat16*)(smem + 18432);
    __nv_bfloat16* sW2 = (__nv_bfloat16*)(smem + 35840);
    __nv_bfloat16* sX  = (__nv_bfloat16*)(smem + 54272);
    float*         sTkf = (float*)(smem + 63488);
    float*         sTvf = (float*)(smem + 80384);
    __nv_bfloat16* sTkb = (__nv_bfloat16*)(smem + 97280);
    __nv_bfloat16* sTvb = (__nv_bfloat16*)(smem + 106496);
    __nv_bfloat16* sHb = (__nv_bfloat16*)(smem + 115712);
    float*         sV  = (float*)(smem + 133120);
    float*         sG  = (float*)(smem + 135680);

    u32 sb = (u32)__cvta_generic_to_shared(smem);
    const u32 sbWk = sb, sbWv = sb + 9216, sbW1 = sb + 18432, sbW2 = sb + 35840;
    const u32 sbX = sb + 54272, sbTkb = sb + 97280, sbTvb = sb + 106496, sbHb = sb + 115712;

    const int t = threadIdx.x, warp = t >> 5, lane = t & 31;
    const int mt = warp >> 1, ng = warp & 1;
    const int l15 = lane & 15, lh = lane >> 4, lr = lane >> 2, lc = (lane & 3) * 2;

    // ---- weight conversion fp32 -> padded bf16 ----
    for (int i = t; i < 4096; i += 256) {
        int r = i >> 6, c = i & 63;
        sWk[r * 72 + c] = __float2bfloat16(Wk[i]);
        sWv[r * 72 + c] = __float2bfloat16(Wv[i]);
    }
    for (int i = t; i < 8192; i += 256) {
        int r1_ = i >> 7, c1_ = i & 127;
        sW1[r1_ * 136 + c1_] = __float2bfloat16(W1[i]);
        int r2_ = i >> 6, c2_ = i & 63;
        sW2[r2_ * 72 + c2_] = __float2bfloat16(W2[i]);
    }
    if (t < 64) {
        sV[t]       = paW[t];
        sV[64 + t]  = paW[64 + t];
        sV[128 + t] = pab[t];
        sV[192 + t] = lng[t];
        sV[256 + t] = lnb[t];
        sV[320 + t] = peg[t];
        sV[384 + t] = peb[t];
        sV[576 + t] = b2[t];
    }
    if (t < 128) sV[448 + t] = b1[t];
    __syncthreads();

    const float *pa0 = sV, *pa1 = sV + 64, *pbv = sV + 128,
                *sing = sV + 192, *sinb = sV + 256,
                *speg = sV + 320, *speb = sV + 384,
                *sb1 = sV + 448, *sb2v = sV + 576;

    for (int ti = 0; ti < 4; ti++) {
        int tile = blockIdx.x * 4 + ti;          // 8192 tiles of 64 rows
        int rowbase = tile * 64;

        // ---- LN of input features (warp-per-row) -> bf16 sX, + grids ----
        for (int rr = warp; rr < 64; rr += 8) {
            const float* rp = inp + (size_t)(rowbase + rr) * 66;
            float x0 = rp[lane], x1 = rp[lane + 32];
            float s1 = x0 + x1, s2 = x0 * x0 + x1 * x1;
            #pragma unroll
            for (int o = 16; o; o >>= 1) {
                s1 += __shfl_xor_sync(0xffffffffu, s1, o);
                s2 += __shfl_xor_sync(0xffffffffu, s2, o);
            }
            float mu = s1 * 0.015625f;
            float var = s2 * 0.015625f - mu * mu;
            float rs = rsqrtf(var + LNEPS);
            sX[rr * 72 + lane]      = __float2bfloat16((x0 - mu) * rs * sing[lane]      + sinb[lane]);
            sX[rr * 72 + lane + 32] = __float2bfloat16((x1 - mu) * rs * sing[lane + 32] + sinb[lane + 32]);
            if (lane < 2) sG[rr * 2 + lane] = rp[64 + lane];
        }
        __syncthreads();

        // ---- GEMM1 (tensor): Tk = X@Wk + gp, Tv = X@Wv + gp ----
        {
            float accK[4][4], accV[4][4];
            #pragma unroll
            for (int s = 0; s < 4; s++)
                #pragma unroll
                for (int j = 0; j < 4; j++) { accK[s][j] = 0.f; accV[s][j] = 0.f; }

            #pragma unroll
            for (int ks = 0; ks < 4; ks++) {
                u32 a[4];
                ldsm_x4(a, sbX + ((mt * 16 + l15) * 72 + ks * 16 + lh * 8) * 2);
                #pragma unroll
                for (int s = 0; s < 4; s++) {
                    u32 bk[2], bv[2];
                    int nb = ng * 32 + s * 8;
                    ldsm_x2t(bk, sbWk + ((ks * 16 + l15) * 72 + nb) * 2);
                    ldsm_x2t(bv, sbWv + ((ks * 16 + l15) * 72 + nb) * 2);
                    mma_bf16(accK[s], a, bk);
                    mma_bf16(accV[s], a, bv);
                }
            }
            int r0 = mt * 16 + lr, r1 = r0 + 8;
            float gx0 = sG[r0 * 2], gy0 = sG[r0 * 2 + 1];
            float gx1 = sG[r1 * 2], gy1 = sG[r1 * 2 + 1];
            #pragma unroll
            for (int s = 0; s < 4; s++) {
                int c = ng * 32 + s * 8 + lc;
                float p0a = pa0[c], p0b = pa0[c + 1];
                float p1a = pa1[c], p1b = pa1[c + 1];
                float pba = pbv[c], pbb = pbv[c + 1];
                float g0a = gx0 * p0a + gy0 * p1a + pba;
                float g0b = gx0 * p0b + gy0 * p1b + pbb;
                float g1a = gx1 * p0a + gy1 * p1a + pba;
                float g1b = gx1 * p0b + gy1 * p1b + pbb;
                *(float2*)&sTkf[r0 * 66 + c] = make_float2(accK[s][0] + g0a, accK[s][1] + g0b);
                *(float2*)&sTkf[r1 * 66 + c] = make_float2(accK[s][2] + g1a, accK[s][3] + g1b);
                *(float2*)&sTvf[r0 * 66 + c] = make_float2(accV[s][0] + g0a, accV[s][1] + g0b);
                *(float2*)&sTvf[r1 * 66 + c] = make_float2(accV[s][2] + g1a, accV[s][3] + g1b);
            }
        }
        __syncthreads();

        // ---- LN (pe) on both T tiles -> bf16 ----
        for (int rr = warp; rr < 64; rr += 8) {
            #pragma unroll
            for (int which = 0; which < 2; which++) {
                const float* Tf = which ? sTvf : sTkf;
                __nv_bfloat16* Tb = which ? sTvb : sTkb;
                float x0 = Tf[rr * 66 + lane], x1 = Tf[rr * 66 + lane + 32];
                float s1 = x0 + x1, s2 = x0 * x0 + x1 * x1;
                #pragma unroll
                for (int o = 16; o; o >>= 1) {
                    s1 += __shfl_xor_sync(0xffffffffu, s1, o);
                    s2 += __shfl_xor_sync(0xffffffffu, s2, o);
                }
                float mu = s1 * 0.015625f;
                float var = s2 * 0.015625f - mu * mu;
                float rs = rsqrtf(var + LNEPS);
                Tb[rr * 72 + lane]      = __float2bfloat16((x0 - mu) * rs * speg[lane]      + speb[lane]);
                Tb[rr * 72 + lane + 32] = __float2bfloat16((x1 - mu) * rs * speg[lane + 32] + speb[lane + 32]);
            }
        }
        __syncthreads();

        #pragma unroll 1
        for (int pass = 0; pass < 2; pass++) {
            const u32 sbT = pass ? sbTvb : sbTkb;
            unsigned* outg = pass ? g_vh : g_kh;

            // ---- GEMM2 (tensor): H = relu(T @ W1 + b1) -> bf16 sH ----
            {
                float acc[8][4];
                #pragma unroll
                for (int s = 0; s < 8; s++)
                    #pragma unroll
                    for (int j = 0; j < 4; j++) acc[s][j] = 0.f;

                #pragma unroll
                for (int ks = 0; ks < 4; ks++) {
                    u32 a[4];
                    ldsm_x4(a, sbT + ((mt * 16 + l15) * 72 + ks * 16 + lh * 8) * 2);
                    #pragma unroll
                    for (int s = 0; s < 8; s++) {
                        u32 b[2];
                        int nb = ng * 64 + s * 8;
                        ldsm_x2t(b, sbW1 + ((ks * 16 + l15) * 136 + nb) * 2);
                        mma_bf16(acc[s], a, b);
                    }
                }
                int r0 = mt * 16 + lr, r1 = r0 + 8;
                #pragma unroll
                for (int s = 0; s < 8; s++) {
                    int c = ng * 64 + s * 8 + lc;
                    float ba = sb1[c], bb = sb1[c + 1];
                    *(u32*)&sHb[r0 * 136 + c] =
                        bf2u(fmaxf(acc[s][0] + ba, 0.f), fmaxf(acc[s][1] + bb, 0.f));
                    *(u32*)&sHb[r1 * 136 + c] =
                        bf2u(fmaxf(acc[s][2] + ba, 0.f), fmaxf(acc[s][3] + bb, 0.f));
                }
            }
            __syncthreads();

            // ---- GEMM3 (tensor): out = H @ W2 + b2 -> bf16x2 gmem ----
            {
                float acc[4][4];
                #pragma unroll
                for (int s = 0; s < 4; s++)
                    #pragma unroll
                    for (int j = 0; j < 4; j++) acc[s][j] = 0.f;

                #pragma unroll
                for (int ks = 0; ks < 8; ks++) {
                    u32 a[4];
                    ldsm_x4(a, sbHb + ((mt * 16 + l15) * 136 + ks * 16 + lh * 8) * 2);
                    #pragma unroll
                    for (int s = 0; s < 4; s++) {
                        u32 b[2];
                        int nb = ng * 32 + s * 8;
                        ldsm_x2t(b, sbW2 + ((ks * 16 + l15) * 72 + nb) * 2);
                        mma_bf16(acc[s], a, b);
                    }
                }
                int r0 = mt * 16 + lr, r1 = r0 + 8;
                #pragma unroll
                for (int s = 0; s < 4; s++) {
                    int c = ng * 32 + s * 8 + lc;
                    float ba = sb2v[c], bb = sb2v[c + 1];
                    outg[(size_t)(rowbase + r0) * 32 + (c >> 1)] =
                        bf2u(acc[s][0] + ba, acc[s][1] + bb);
                    outg[(size_t)(rowbase + r1) * 32 + (c >> 1)] =
                        bf2u(acc[s][2] + ba, acc[s][3] + bb);
                }
            }
            __syncthreads();
        }
    }
}

// ---------------------------------------------------------------------------
// Kernel 2: init slot state
// ---------------------------------------------------------------------------
__global__ void init_slots_kernel(const float* __restrict__ slots)
{
    g_s[blockIdx.x * 512 + threadIdx.x] = slots[threadIdx.x];
}

// ---------------------------------------------------------------------------
// Kernel 3: q = LN(s; ln_s) @ Wq  (one block per b)
// ---------------------------------------------------------------------------
__global__ __launch_bounds__(256) void slotq_kernel(
    const float* __restrict__ lnsg, const float* __restrict__ lnsb,
    const float* __restrict__ Wq)
{
    __shared__ float sln[512];
    int b = blockIdx.x, t = threadIdx.x, warp = t >> 5, lane = t & 31;
    {
        const float* row = g_s + b * 512 + warp * 64;
        float x0 = row[lane], x1 = row[lane + 32];
        float s1 = x0 + x1, s2 = x0 * x0 + x1 * x1;
        #pragma unroll
        for (int o = 16; o; o >>= 1) {
            s1 += __shfl_xor_sync(0xffffffffu, s1, o);
            s2 += __shfl_xor_sync(0xffffffffu, s2, o);
        }
        float mu = s1 * 0.015625f;
        float var = s2 * 0.015625f - mu * mu;
        float rs = rsqrtf(var + LNEPS);
        sln[warp * 64 + lane]      = (x0 - mu) * rs * lnsg[lane]      + lnsb[lane];
        sln[warp * 64 + lane + 32] = (x1 - mu) * rs * lnsg[lane + 32] + lnsb[lane + 32];
    }
    __syncthreads();
    for (int i = t; i < 512; i += 256) {
        int s = i >> 6, c = i & 63;
        float a = 0.f;
        #pragma unroll 8
        for (int d = 0; d < 64; d++) a += sln[s * 64 + d] * Wq[d * 64 + c];
        g_q[b * 512 + i] = a;
    }
}

// ---------------------------------------------------------------------------
// Kernel 4: attention, shuffle-free (unchanged from best passing version).
// ---------------------------------------------------------------------------
#define ATTN_SMEM_FLOATS 23360

__global__ __launch_bounds__(256) void attn_kernel()
{
    extern __shared__ float sm[];
    float* qT   = sm;                  // [64][8]
    float* sKb  = sm + 512;            // per-warp [32][65]
    float* sAb  = sm + 17152;          // per-warp [32][8]
    float* wacc = sm + 19200;          // [8][520]

    int b = blockIdx.x >> 6, pb = blockIdx.x & 63;
    int t = threadIdx.x, warp = t >> 5, lane = t & 31;

    for (int i = t; i < 512; i += 256) {
        int s = i >> 6, d = i & 63;
        qT[d * 8 + s] = g_q[b * 512 + i];
    }
    __syncthreads();

    size_t rowbase = (size_t)b * N_ + pb * 256 + warp * 32;
    const unsigned* kp = g_kh + rowbase * 32;
    const unsigned* vp = g_vh + rowbase * 32;

    float* mk = sKb + warp * 2080;
    #pragma unroll 4
    for (int i = 0; i < 32; i++) {
        float2 f = u2f2(kp[i * 32 + lane]);
        mk[i * 65 + lane * 2]     = f.x;
        mk[i * 65 + lane * 2 + 1] = f.y;
    }
    __syncwarp();

    float lg[8];
    #pragma unroll
    for (int s = 0; s < 8; s++) lg[s] = 0.f;
    {
        const float* myk = mk + lane * 65;
        #pragma unroll 8
        for (int d = 0; d < 64; d++) {
            float kd = myk[d];
            float4 qa = *(const float4*)(qT + d * 8);
            float4 qb = *(const float4*)(qT + d * 8 + 4);
            lg[0] += kd * qa.x; lg[1] += kd * qa.y;
            lg[2] += kd * qa.z; lg[3] += kd * qa.w;
            lg[4] += kd * qb.x; lg[5] += kd * qb.y;
            lg[6] += kd * qb.z; lg[7] += kd * qb.w;
        }
    }
    float den8[8];
    {
        #pragma unroll
        for (int s = 0; s < 8; s++) lg[s] *= 0.125f;
        float mx = lg[0];
        #pragma unroll
        for (int s = 1; s < 8; s++) mx = fmaxf(mx, lg[s]);
        float se = 0.f;
        #pragma unroll
        for (int s = 0; s < 8; s++) { lg[s] = __expf(lg[s] - mx); se += lg[s]; }
        float inv = 1.f / se;
        #pragma unroll
        for (int s = 0; s < 8; s++) { lg[s] = lg[s] * inv + ATTN_EPS; den8[s] = lg[s]; }
        float* pa = sAb + warp * 256 + lane * 8;
        *(float4*)pa = make_float4(lg[0], lg[1], lg[2], lg[3]);
        *(float4*)(pa + 4) = make_float4(lg[4], lg[5], lg[6], lg[7]);
    }
    __syncwarp();

    float acc0[8], acc1[8];
    #pragma unroll
    for (int s = 0; s < 8; s++) { acc0[s] = 0.f; acc1[s] = 0.f; }
    {
        const float* pa = sAb + warp * 256;
        #pragma unroll 4
        for (int i = 0; i < 32; i++) {
            float2 v = u2f2(vp[i * 32 + lane]);
            float4 a0 = *(const float4*)(pa + i * 8);
            float4 a1 = *(const float4*)(pa + i * 8 + 4);
            acc0[0] += a0.x * v.x; acc1[0] += a0.x * v.y;
            acc0[1] += a0.y * v.x; acc1[1] += a0.y * v.y;
            acc0[2] += a0.z * v.x; acc1[2] += a0.z * v.y;
            acc0[3] += a0.w * v.x; acc1[3] += a0.w * v.y;
            acc0[4] += a1.x * v.x; acc1[4] += a1.x * v.y;
            acc0[5] += a1.y * v.x; acc1[5] += a1.y * v.y;
            acc0[6] += a1.z * v.x; acc1[6] += a1.z * v.y;
            acc0[7] += a1.w * v.x; acc1[7] += a1.w * v.y;
        }
    }
    #pragma unroll
    for (int s = 0; s < 8; s++) {
        float d = den8[s];
        #pragma unroll
        for (int o = 16; o; o >>= 1) d += __shfl_xor_sync(0xffffffffu, d, o);
        den8[s] = d;
    }

    float* wa = wacc + warp * 520;
    #pragma unroll
    for (int s = 0; s < 8; s++) {
        wa[s * 64 + lane * 2]     = acc0[s];
        wa[s * 64 + lane * 2 + 1] = acc1[s];
    }
    if (lane == 0) {
        #pragma unroll
        for (int s = 0; s < 8; s++) wa[512 + s] = den8[s];
    }
    __syncthreads();

    float* dst = g_part + (size_t)blockIdx.x * 520;
    for (int i = t; i < 520; i += 256) {
        float v = 0.f;
        #pragma unroll
        for (int w = 0; w < 8; w++) v += wacc[w * 520 + i];
        dst[i] = v;
    }
}

// ---------------------------------------------------------------------------
// Kernel 5: reduce partials -> updates -> GRU -> MLP residual (one block/b)
// ---------------------------------------------------------------------------
__global__ __launch_bounds__(256) void update_kernel(
    const float* __restrict__ W_ih, const float* __restrict__ W_hh,
    const float* __restrict__ b_ih, const float* __restrict__ b_hh,
    const float* __restrict__ lnmg, const float* __restrict__ lnmb,
    const float* __restrict__ mW1,  const float* __restrict__ mb1,
    const float* __restrict__ mW2,  const float* __restrict__ mb2,
    float* __restrict__ dout)
{
    __shared__ float red[520];
    __shared__ float u[512], prev[512], gx[1536], gh[1536];
    __shared__ float snew[512], sln[512], h1[1024];
    int b = blockIdx.x, t = threadIdx.x, warp = t >> 5, lane = t & 31;

    for (int i = t; i < 520; i += 256) {
        float v = 0.f;
        const float* p = g_part + (size_t)(b * 64) * 520 + i;
        #pragma unroll 8
        for (int pp = 0; pp < 64; pp++) v += p[pp * 520];
        red[i] = v;
    }
    for (int i = t; i < 512; i += 256) prev[i] = g_s[b * 512 + i];
    __syncthreads();

    for (int i = t; i < 512; i += 256) u[i] = red[i] / red[512 + (i >> 6)];
    __syncthreads();

    for (int i = t; i < 1536; i += 256) {
        int s = i / 192, j = i - s * 192;
        float ax = b_ih[j], ah = b_hh[j];
        const float* us = u + s * 64;
        const float* ps = prev + s * 64;
        #pragma unroll 8
        for (int d = 0; d < 64; d++) {
            ax += us[d] * W_ih[d * 192 + j];
            ah += ps[d] * W_hh[d * 192 + j];
        }
        gx[i] = ax; gh[i] = ah;
    }
    __syncthreads();

    for (int i = t; i < 512; i += 256) {
        int s = i >> 6, dd = i & 63;
        float xr = gx[s * 192 + dd], xz = gx[s * 192 + 64 + dd], xn = gx[s * 192 + 128 + dd];
        float hr = gh[s * 192 + dd], hz = gh[s * 192 + 64 + dd], hn = gh[s * 192 + 128 + dd];
        float r_ = 1.f / (1.f + __expf(-(xr + hr)));
        float z  = 1.f / (1.f + __expf(-(xz + hz)));
        float nn = tanhf(xn + r_ * hn);
        snew[i] = (1.f - z) * nn + z * prev[i];
    }
    __syncthreads();

    {
        const float* row = snew + warp * 64;
        float x0 = row[lane], x1 = row[lane + 32];
        float s1 = x0 + x1, s2 = x0 * x0 + x1 * x1;
        #pragma unroll
        for (int o = 16; o; o >>= 1) {
            s1 += __shfl_xor_sync(0xffffffffu, s1, o);
            s2 += __shfl_xor_sync(0xffffffffu, s2, o);
        }
        float mu = s1 * 0.015625f;
        float var = s2 * 0.015625f - mu * mu;
        float rs = rsqrtf(var + LNEPS);
        sln[warp * 64 + lane]      = (x0 - mu) * rs * lnmg[lane]      + lnmb[lane];
        sln[warp * 64 + lane + 32] = (x1 - mu) * rs * lnmg[lane + 32] + lnmb[lane + 32];
    }
    __syncthreads();

    for (int i = t; i < 1024; i += 256) {
        int s = i >> 7, j = i & 127;
        float a = mb1[j];
        const float* r = sln + s * 64;
        #pragma unroll 8
        for (int d = 0; d < 64; d++) a += r[d] * mW1[d * 128 + j];
        h1[i] = fmaxf(a, 0.f);
    }
    __syncthreads();

    for (int i = t; i < 512; i += 256) {
        int s = i >> 6, c = i & 63;
        float a = mb2[c];
        const float* r = h1 + s * 128;
        #pragma unroll 8
        for (int k = 0; k < 128; k++) a += r[k] * mW2[k * 64 + c];
        float val = snew[i] + a;
        g_s[b * 512 + i] = val;
        dout[b * 512 + i] = val;
    }
}

// ---------------------------------------------------------------------------
extern "C" void kernel_launch(void* const* d_in, const int* in_sizes, int n_in,
                              void* d_out, int out_size)
{
    (void)in_sizes; (void)n_in; (void)out_size;
    const float* inputs  = (const float*)d_in[0];
    const float* slots   = (const float*)d_in[1];
    const float* ln_in_g = (const float*)d_in[2];
    const float* ln_in_b = (const float*)d_in[3];
    const float* ln_s_g  = (const float*)d_in[4];
    const float* ln_s_b  = (const float*)d_in[5];
    const float* ln_m_g  = (const float*)d_in[6];
    const float* ln_m_b  = (const float*)d_in[7];
    const float* Wq      = (const float*)d_in[8];
    const float* Wk      = (const float*)d_in[9];
    const float* Wv      = (const float*)d_in[10];
    const float* W_ih    = (const float*)d_in[11];
    const float* W_hh    = (const float*)d_in[12];
    const float* b_ih    = (const float*)d_in[13];
    const float* b_hh    = (const float*)d_in[14];
    const float* mlp_W1  = (const float*)d_in[15];
    const float* mlp_b1  = (const float*)d_in[16];
    const float* mlp_W2  = (const float*)d_in[17];
    const float* mlp_b2  = (const float*)d_in[18];
    const float* pa_W    = (const float*)d_in[19];
    const float* pa_b    = (const float*)d_in[20];
    const float* pe_g    = (const float*)d_in[21];
    const float* pe_b    = (const float*)d_in[22];
    const float* pe_W1   = (const float*)d_in[23];
    const float* pe_b1   = (const float*)d_in[24];
    const float* pe_W2   = (const float*)d_in[25];
    const float* pe_b2   = (const float*)d_in[26];
    float* out = (float*)d_out;

    static int configured = 0;
    const int attn_smem = ATTN_SMEM_FLOATS * 4;
    if (!configured) {
        cudaFuncSetAttribute(preprocess_kernel,
                             cudaFuncAttributeMaxDynamicSharedMemorySize, PRE_SMEM_BYTES);
        cudaFuncSetAttribute(attn_kernel,
                             cudaFuncAttributeMaxDynamicSharedMemorySize, attn_smem);
        configured = 1;
    }

    preprocess_kernel<<<2048, 256, PRE_SMEM_BYTES>>>(
        inputs, ln_in_g, ln_in_b, Wk, Wv, pa_W, pa_b, pe_g, pe_b,
        pe_W1, pe_b1, pe_W2, pe_b2);

    init_slots_kernel<<<32, 512>>>(slots);

    for (int it = 0; it < 3; it++) {
        slotq_kernel<<<32, 256>>>(ln_s_g, ln_s_b, Wq);
        attn_kernel<<<2048, 256, attn_smem>>>();
        update_kernel<<<32, 256>>>(W_ih, W_hh, b_ih, b_hh,
                                   ln_m_g, ln_m_b,
                                   mlp_W1, mlp_b1, mlp_W2, mlp_b2, out);
    }
}

// round 9
// speedup vs baseline: 2.0986x; 1.2819x over previous
#include <cuda_runtime.h>
#include <cuda_bf16.h>
#include <cmath>

#define B_ 32
#define N_ 16384
#define D_ 64
#define S_ 8
#define H_ 128
#define LNEPS 1e-5f
#define ATTN_EPS 1e-8f

typedef unsigned long long ull;
typedef unsigned int u32;

// ---------------- scratch (device globals; no allocations allowed) ----------
__device__ unsigned g_kh[B_ * N_ * 32];   // k_pos as bf16x2 pairs (64 MB)
__device__ unsigned g_vh[B_ * N_ * 32];   // v_pos as bf16x2 pairs (64 MB)
__device__ float g_q[B_ * S_ * D_];
__device__ float g_s[B_ * S_ * D_];
__device__ float g_part[B_ * 64 * 520];   // per-(b, partial-block) numer(512)+den(8)

// ---------------- helpers ----------------------------------------------------
__device__ __forceinline__ unsigned bf2u(float a, float b) {
    __nv_bfloat162 h = __float22bfloat162_rn(make_float2(a, b));
    return *(unsigned*)&h;
}
__device__ __forceinline__ float2 u2f2(unsigned u) {
    __nv_bfloat162 h = *(__nv_bfloat162*)&u;
    return __bfloat1622float2(h);
}
__device__ __forceinline__ void ldsm_x4(u32 a[4], u32 addr) {
    asm volatile("ldmatrix.sync.aligned.m8n8.x4.shared.b16 {%0,%1,%2,%3}, [%4];"
                 : "=r"(a[0]), "=r"(a[1]), "=r"(a[2]), "=r"(a[3]) : "r"(addr));
}
__device__ __forceinline__ void ldsm_x2t(u32 b[2], u32 addr) {
    asm volatile("ldmatrix.sync.aligned.m8n8.x2.trans.shared.b16 {%0,%1}, [%2];"
                 : "=r"(b[0]), "=r"(b[1]) : "r"(addr));
}
__device__ __forceinline__ void mma_bf16(float d[4], const u32 a[4], const u32 b[2]) {
    asm volatile("mma.sync.aligned.m16n8k16.row.col.f32.bf16.bf16.f32 "
                 "{%0,%1,%2,%3},{%4,%5,%6,%7},{%8,%9},{%0,%1,%2,%3};"
                 : "+f"(d[0]), "+f"(d[1]), "+f"(d[2]), "+f"(d[3])
                 : "r"(a[0]), "r"(a[1]), "r"(a[2]), "r"(a[3]), "r"(b[0]), "r"(b[1]));
}

// ---------------------------------------------------------------------------
// Kernel 1: fused preprocessing, bf16 HMMA, two passes (k then v) per tile so
// smem fits 2 CTAs/SM.
// smem byte layout:
//   Wk_b @      0 : 64x72  bf16 =  9216
//   Wv_b @   9216 : 64x72  bf16 =  9216
//   W1_b @  18432 : 64x136 bf16 = 17408
//   W2_b @  35840 : 128x72 bf16 = 18432
//   X_b  @  54272 : 64x72  bf16 =  9216      (alive across both passes)
//   Tf/H @  63488 : 17408 region  (Tf: 64x66 f32 = 16896; later H: 64x136 bf16)
//   Tb   @  80896 : 64x72  bf16 =  9216
//   V_f  @  90112 : 640 f32      =  2560
//   G_f  @  92672 : 128 f32      =   512     -> total 93184 B  (2 CTAs/SM)
// ---------------------------------------------------------------------------
#define PRE_SMEM_BYTES 93184

__global__ __launch_bounds__(256, 2) void preprocess_kernel(
    const float* __restrict__ inp,
    const float* __restrict__ lng, const float* __restrict__ lnb,
    const float* __restrict__ Wk,  const float* __restrict__ Wv,
    const float* __restrict__ paW, const float* __restrict__ pab,
    const float* __restrict__ peg, const float* __restrict__ peb,
    const float* __restrict__ W1,  const float* __restrict__ b1,
    const float* __restrict__ W2,  const float* __restrict__ b2)
{
    extern __shared__ char smem[];
    __nv_bfloat16* sWk = (__nv_bfloat16*)(smem);
    __nv_bfloat16* sWv = (__nv_bfloat16*)(smem + 9216);
    __nv_bfloat16* sW1 = (__nv_bfloat16*)(smem + 18432);
    __nv_bfloat16* sW2 = (__nv_bfloat16*)(smem + 35840);
    __nv_bfloat16* sX  = (__nv_bfloat16*)(smem + 54272);
    float*         sTf = (float*)(smem + 63488);          // aliased with sHb
    __nv_bfloat16* sHb = (__nv_bfloat16*)(smem + 63488);
    __nv_bfloat16* sTb = (__nv_bfloat16*)(smem + 80896);
    float*         sV  = (float*)(smem + 90112);
    float*         sG  = (float*)(smem + 92672);

    u32 sb = (u32)__cvta_generic_to_shared(smem);
    const u32 sbWk = sb, sbWv = sb + 9216, sbW1 = sb + 18432, sbW2 = sb + 35840;
    const u32 sbX = sb + 54272, sbHb = sb + 63488, sbTb = sb + 80896;

    const int t = threadIdx.x, warp = t >> 5, lane = t & 31;
    const int mt = warp >> 1, ng = warp & 1;
    const int l15 = lane & 15, lh = lane >> 4, lr = lane >> 2, lc = (lane & 3) * 2;

    // ---- weight conversion fp32 -> padded bf16 ----
    for (int i = t; i < 4096; i += 256) {
        int r = i >> 6, c = i & 63;
        sWk[r * 72 + c] = __float2bfloat16(Wk[i]);
        sWv[r * 72 + c] = __float2bfloat16(Wv[i]);
    }
    for (int i = t; i < 8192; i += 256) {
        int r1_ = i >> 7, c1_ = i & 127;
        sW1[r1_ * 136 + c1_] = __float2bfloat16(W1[i]);
        int r2_ = i >> 6, c2_ = i & 63;
        sW2[r2_ * 72 + c2_] = __float2bfloat16(W2[i]);
    }
    if (t < 64) {
        sV[t]       = paW[t];
        sV[64 + t]  = paW[64 + t];
        sV[128 + t] = pab[t];
        sV[192 + t] = lng[t];
        sV[256 + t] = lnb[t];
        sV[320 + t] = peg[t];
        sV[384 + t] = peb[t];
        sV[576 + t] = b2[t];
    }
    if (t < 128) sV[448 + t] = b1[t];
    __syncthreads();

    const float *pa0 = sV, *pa1 = sV + 64, *pbv = sV + 128,
                *sing = sV + 192, *sinb = sV + 256,
                *speg = sV + 320, *speb = sV + 384,
                *sb1 = sV + 448, *sb2v = sV + 576;

    for (int ti = 0; ti < 4; ti++) {
        int tile = blockIdx.x * 4 + ti;          // 8192 tiles of 64 rows
        int rowbase = tile * 64;

        // ---- LN of input features (warp-per-row) -> bf16 sX, + grids ----
        for (int rr = warp; rr < 64; rr += 8) {
            const float* rp = inp + (size_t)(rowbase + rr) * 66;
            float x0 = rp[lane], x1 = rp[lane + 32];
            float s1 = x0 + x1, s2 = x0 * x0 + x1 * x1;
            #pragma unroll
            for (int o = 16; o; o >>= 1) {
                s1 += __shfl_xor_sync(0xffffffffu, s1, o);
                s2 += __shfl_xor_sync(0xffffffffu, s2, o);
            }
            float mu = s1 * 0.015625f;
            float var = s2 * 0.015625f - mu * mu;
            float rs = rsqrtf(var + LNEPS);
            sX[rr * 72 + lane]      = __float2bfloat16((x0 - mu) * rs * sing[lane]      + sinb[lane]);
            sX[rr * 72 + lane + 32] = __float2bfloat16((x1 - mu) * rs * sing[lane + 32] + sinb[lane + 32]);
            if (lane < 2) sG[rr * 2 + lane] = rp[64 + lane];
        }
        __syncthreads();

        #pragma unroll 1
        for (int pass = 0; pass < 2; pass++) {
            const u32 sbW = pass ? sbWv : sbWk;
            unsigned* outg = pass ? g_vh : g_kh;

            // ---- GEMM1 (tensor): Tf = X@W + gridproj ----
            {
                float acc[4][4];
                #pragma unroll
                for (int s = 0; s < 4; s++)
                    #pragma unroll
                    for (int j = 0; j < 4; j++) acc[s][j] = 0.f;

                #pragma unroll
                for (int ks = 0; ks < 4; ks++) {
                    u32 a[4];
                    ldsm_x4(a, sbX + ((mt * 16 + l15) * 72 + ks * 16 + lh * 8) * 2);
                    #pragma unroll
                    for (int s = 0; s < 4; s++) {
                        u32 b[2];
                        int nb = ng * 32 + s * 8;
                        ldsm_x2t(b, sbW + ((ks * 16 + l15) * 72 + nb) * 2);
                        mma_bf16(acc[s], a, b);
                    }
                }
                int r0 = mt * 16 + lr, r1 = r0 + 8;
                float gx0 = sG[r0 * 2], gy0 = sG[r0 * 2 + 1];
                float gx1 = sG[r1 * 2], gy1 = sG[r1 * 2 + 1];
                #pragma unroll
                for (int s = 0; s < 4; s++) {
                    int c = ng * 32 + s * 8 + lc;
                    float p0a = pa0[c], p0b = pa0[c + 1];
                    float p1a = pa1[c], p1b = pa1[c + 1];
                    float pba = pbv[c], pbb = pbv[c + 1];
                    *(float2*)&sTf[r0 * 66 + c] =
                        make_float2(acc[s][0] + gx0 * p0a + gy0 * p1a + pba,
                                    acc[s][1] + gx0 * p0b + gy0 * p1b + pbb);
                    *(float2*)&sTf[r1 * 66 + c] =
                        make_float2(acc[s][2] + gx1 * p0a + gy1 * p1a + pba,
                                    acc[s][3] + gx1 * p0b + gy1 * p1b + pbb);
                }
            }
            __syncthreads();

            // ---- LN (pe) -> bf16 Tb ----
            for (int rr = warp; rr < 64; rr += 8) {
                float x0 = sTf[rr * 66 + lane], x1 = sTf[rr * 66 + lane + 32];
                float s1 = x0 + x1, s2 = x0 * x0 + x1 * x1;
                #pragma unroll
                for (int o = 16; o; o >>= 1) {
                    s1 += __shfl_xor_sync(0xffffffffu, s1, o);
                    s2 += __shfl_xor_sync(0xffffffffu, s2, o);
                }
                float mu = s1 * 0.015625f;
                float var = s2 * 0.015625f - mu * mu;
                float rs = rsqrtf(var + LNEPS);
                sTb[rr * 72 + lane]      = __float2bfloat16((x0 - mu) * rs * speg[lane]      + speb[lane]);
                sTb[rr * 72 + lane + 32] = __float2bfloat16((x1 - mu) * rs * speg[lane + 32] + speb[lane + 32]);
            }
            __syncthreads();

            // ---- GEMM2 (tensor): H = relu(Tb @ W1 + b1) -> bf16 sHb (alias Tf) ----
            {
                float acc[8][4];
                #pragma unroll
                for (int s = 0; s < 8; s++)
                    #pragma unroll
                    for (int j = 0; j < 4; j++) acc[s][j] = 0.f;

                #pragma unroll
                for (int ks = 0; ks < 4; ks++) {
                    u32 a[4];
                    ldsm_x4(a, sbTb + ((mt * 16 + l15) * 72 + ks * 16 + lh * 8) * 2);
                    #pragma unroll
                    for (int s = 0; s < 8; s++) {
                        u32 b[2];
                        int nb = ng * 64 + s * 8;
                        ldsm_x2t(b, sbW1 + ((ks * 16 + l15) * 136 + nb) * 2);
                        mma_bf16(acc[s], a, b);
                    }
                }
                __syncthreads();   // Tf reads done before H overwrite (alias safety)
                int r0 = mt * 16 + lr, r1 = r0 + 8;
                #pragma unroll
                for (int s = 0; s < 8; s++) {
                    int c = ng * 64 + s * 8 + lc;
                    float ba = sb1[c], bb = sb1[c + 1];
                    *(u32*)&sHb[r0 * 136 + c] =
                        bf2u(fmaxf(acc[s][0] + ba, 0.f), fmaxf(acc[s][1] + bb, 0.f));
                    *(u32*)&sHb[r1 * 136 + c] =
                        bf2u(fmaxf(acc[s][2] + ba, 0.f), fmaxf(acc[s][3] + bb, 0.f));
                }
            }
            __syncthreads();

            // ---- GEMM3 (tensor): out = H @ W2 + b2 -> bf16x2 gmem ----
            {
                float acc[4][4];
                #pragma unroll
                for (int s = 0; s < 4; s++)
                    #pragma unroll
                    for (int j = 0; j < 4; j++) acc[s][j] = 0.f;

                #pragma unroll
                for (int ks = 0; ks < 8; ks++) {
                    u32 a[4];
                    ldsm_x4(a, sbHb + ((mt * 16 + l15) * 136 + ks * 16 + lh * 8) * 2);
                    #pragma unroll
                    for (int s = 0; s < 4; s++) {
                        u32 b[2];
                        int nb = ng * 32 + s * 8;
                        ldsm_x2t(b, sbW2 + ((ks * 16 + l15) * 72 + nb) * 2);
                        mma_bf16(acc[s], a, b);
                    }
                }
                int r0 = mt * 16 + lr, r1 = r0 + 8;
                #pragma unroll
                for (int s = 0; s < 4; s++) {
                    int c = ng * 32 + s * 8 + lc;
                    float ba = sb2v[c], bb = sb2v[c + 1];
                    outg[(size_t)(rowbase + r0) * 32 + (c >> 1)] =
                        bf2u(acc[s][0] + ba, acc[s][1] + bb);
                    outg[(size_t)(rowbase + r1) * 32 + (c >> 1)] =
                        bf2u(acc[s][2] + ba, acc[s][3] + bb);
                }
            }
            __syncthreads();   // H dead before next pass's GEMM1 writes Tf
        }
    }
}

// ---------------------------------------------------------------------------
// Kernel 2: init slot state
// ---------------------------------------------------------------------------
__global__ void init_slots_kernel(const float* __restrict__ slots)
{
    g_s[blockIdx.x * 512 + threadIdx.x] = slots[threadIdx.x];
}

// ---------------------------------------------------------------------------
// Kernel 3: q = LN(s; ln_s) @ Wq  (one block per b)
// ---------------------------------------------------------------------------
__global__ __launch_bounds__(256) void slotq_kernel(
    const float* __restrict__ lnsg, const float* __restrict__ lnsb,
    const float* __restrict__ Wq)
{
    __shared__ float sln[512];
    int b = blockIdx.x, t = threadIdx.x, warp = t >> 5, lane = t & 31;
    {
        const float* row = g_s + b * 512 + warp * 64;
        float x0 = row[lane], x1 = row[lane + 32];
        float s1 = x0 + x1, s2 = x0 * x0 + x1 * x1;
        #pragma unroll
        for (int o = 16; o; o >>= 1) {
            s1 += __shfl_xor_sync(0xffffffffu, s1, o);
            s2 += __shfl_xor_sync(0xffffffffu, s2, o);
        }
        float mu = s1 * 0.015625f;
        float var = s2 * 0.015625f - mu * mu;
        float rs = rsqrtf(var + LNEPS);
        sln[warp * 64 + lane]      = (x0 - mu) * rs * lnsg[lane]      + lnsb[lane];
        sln[warp * 64 + lane + 32] = (x1 - mu) * rs * lnsg[lane + 32] + lnsb[lane + 32];
    }
    __syncthreads();
    for (int i = t; i < 512; i += 256) {
        int s = i >> 6, c = i & 63;
        float a = 0.f;
        #pragma unroll 8
        for (int d = 0; d < 64; d++) a += sln[s * 64 + d] * Wq[d * 64 + c];
        g_q[b * 512 + i] = a;
    }
}

// ---------------------------------------------------------------------------
// Kernel 4: attention, shuffle-free; k staged in smem as raw bf16x2 (lossless).
// smem bytes: qT f32 @0 (2048) | sKu u32 [8][32*33] @2048 (33792) |
//             sAb f32 [8][256] @35840 (8192) | wacc f32 [8][520] @44032 (16640)
//             -> total 60672 B  (3 CTAs/SM)
// ---------------------------------------------------------------------------
#define ATTN_SMEM_BYTES 60672

__global__ __launch_bounds__(256) void attn_kernel()
{
    extern __shared__ char smc[];
    float* qT   = (float*)smc;              // [64][8]
    u32*   sKu  = (u32*)(smc + 2048);       // per-warp [32][33]
    float* sAb  = (float*)(smc + 35840);    // per-warp [32][8]
    float* wacc = (float*)(smc + 44032);    // [8][520]

    int b = blockIdx.x >> 6, pb = blockIdx.x & 63;
    int t = threadIdx.x, warp = t >> 5, lane = t & 31;

    for (int i = t; i < 512; i += 256) {
        int s = i >> 6, d = i & 63;
        qT[d * 8 + s] = g_q[b * 512 + i];
    }
    __syncthreads();

    size_t rowbase = (size_t)b * N_ + pb * 256 + warp * 32;
    const unsigned* kp = g_kh + rowbase * 32;
    const unsigned* vp = g_vh + rowbase * 32;

    // ---- stage k tile (raw bf16x2, pad 33 -> conflict-free row reads) ----
    u32* mk = sKu + warp * 1056;
    #pragma unroll 4
    for (int i = 0; i < 32; i++) mk[i * 33 + lane] = kp[i * 32 + lane];
    __syncwarp();

    // ---- logits for own row (row = lane) ----
    float lg[8];
    #pragma unroll
    for (int s = 0; s < 8; s++) lg[s] = 0.f;
    {
        const u32* myk = mk + lane * 33;
        #pragma unroll 8
        for (int j = 0; j < 32; j++) {
            float2 kf = u2f2(myk[j]);
            int d0 = j * 2;
            float4 qa = *(const float4*)(qT + d0 * 8);
            float4 qb = *(const float4*)(qT + d0 * 8 + 4);
            lg[0] += kf.x * qa.x; lg[1] += kf.x * qa.y;
            lg[2] += kf.x * qa.z; lg[3] += kf.x * qa.w;
            lg[4] += kf.x * qb.x; lg[5] += kf.x * qb.y;
            lg[6] += kf.x * qb.z; lg[7] += kf.x * qb.w;
            float4 qc = *(const float4*)(qT + d0 * 8 + 8);
            float4 qd = *(const float4*)(qT + d0 * 8 + 12);
            lg[0] += kf.y * qc.x; lg[1] += kf.y * qc.y;
            lg[2] += kf.y * qc.z; lg[3] += kf.y * qc.w;
            lg[4] += kf.y * qd.x; lg[5] += kf.y * qd.y;
            lg[6] += kf.y * qd.z; lg[7] += kf.y * qd.w;
        }
    }
    // ---- per-lane softmax over S=8, + eps ----
    float den8[8];
    {
        #pragma unroll
        for (int s = 0; s < 8; s++) lg[s] *= 0.125f;
        float mx = lg[0];
        #pragma unroll
        for (int s = 1; s < 8; s++) mx = fmaxf(mx, lg[s]);
        float se = 0.f;
        #pragma unroll
        for (int s = 0; s < 8; s++) { lg[s] = __expf(lg[s] - mx); se += lg[s]; }
        float inv = 1.f / se;
        #pragma unroll
        for (int s = 0; s < 8; s++) { lg[s] = lg[s] * inv + ATTN_EPS; den8[s] = lg[s]; }
        float* pa = sAb + warp * 256 + lane * 8;
        *(float4*)pa = make_float4(lg[0], lg[1], lg[2], lg[3]);
        *(float4*)(pa + 4) = make_float4(lg[4], lg[5], lg[6], lg[7]);
    }
    __syncwarp();

    // ---- accumulate numer[s][2 cols per lane] over the 32 rows ----
    float acc0[8], acc1[8];
    #pragma unroll
    for (int s = 0; s < 8; s++) { acc0[s] = 0.f; acc1[s] = 0.f; }
    {
        const float* pa = sAb + warp * 256;
        #pragma unroll 4
        for (int i = 0; i < 32; i++) {
            float2 v = u2f2(vp[i * 32 + lane]);
            float4 a0 = *(const float4*)(pa + i * 8);
            float4 a1 = *(const float4*)(pa + i * 8 + 4);
            acc0[0] += a0.x * v.x; acc1[0] += a0.x * v.y;
            acc0[1] += a0.y * v.x; acc1[1] += a0.y * v.y;
            acc0[2] += a0.z * v.x; acc1[2] += a0.z * v.y;
            acc0[3] += a0.w * v.x; acc1[3] += a0.w * v.y;
            acc0[4] += a1.x * v.x; acc1[4] += a1.x * v.y;
            acc0[5] += a1.y * v.x; acc1[5] += a1.y * v.y;
            acc0[6] += a1.z * v.x; acc1[6] += a1.z * v.y;
            acc0[7] += a1.w * v.x; acc1[7] += a1.w * v.y;
        }
    }
    #pragma unroll
    for (int s = 0; s < 8; s++) {
        float d = den8[s];
        #pragma unroll
        for (int o = 16; o; o >>= 1) d += __shfl_xor_sync(0xffffffffu, d, o);
        den8[s] = d;
    }

    float* wa = wacc + warp * 520;
    #pragma unroll
    for (int s = 0; s < 8; s++) {
        wa[s * 64 + lane * 2]     = acc0[s];
        wa[s * 64 + lane * 2 + 1] = acc1[s];
    }
    if (lane == 0) {
        #pragma unroll
        for (int s = 0; s < 8; s++) wa[512 + s] = den8[s];
    }
    __syncthreads();

    float* dst = g_part + (size_t)blockIdx.x * 520;
    for (int i = t; i < 520; i += 256) {
        float v = 0.f;
        #pragma unroll
        for (int w = 0; w < 8; w++) v += wacc[w * 520 + i];
        dst[i] = v;
    }
}

// ---------------------------------------------------------------------------
// Kernel 5: reduce partials -> updates -> GRU -> MLP residual (one block/b)
// ---------------------------------------------------------------------------
__global__ __launch_bounds__(256) void update_kernel(
    const float* __restrict__ W_ih, const float* __restrict__ W_hh,
    const float* __restrict__ b_ih, const float* __restrict__ b_hh,
    const float* __restrict__ lnmg, const float* __restrict__ lnmb,
    const float* __restrict__ mW1,  const float* __restrict__ mb1,
    const float* __restrict__ mW2,  const float* __restrict__ mb2,
    float* __restrict__ dout)
{
    __shared__ float red[520];
    __shared__ float u[512], prev[512], gx[1536], gh[1536];
    __shared__ float snew[512], sln[512], h1[1024];
    int b = blockIdx.x, t = threadIdx.x, warp = t >> 5, lane = t & 31;

    for (int i = t; i < 520; i += 256) {
        float v = 0.f;
        const float* p = g_part + (size_t)(b * 64) * 520 + i;
        #pragma unroll 8
        for (int pp = 0; pp < 64; pp++) v += p[pp * 520];
        red[i] = v;
    }
    for (int i = t; i < 512; i += 256) prev[i] = g_s[b * 512 + i];
    __syncthreads();

    for (int i = t; i < 512; i += 256) u[i] = red[i] / red[512 + (i >> 6)];
    __syncthreads();

    for (int i = t; i < 1536; i += 256) {
        int s = i / 192, j = i - s * 192;
        float ax = b_ih[j], ah = b_hh[j];
        const float* us = u + s * 64;
        const float* ps = prev + s * 64;
        #pragma unroll 8
        for (int d = 0; d < 64; d++) {
            ax += us[d] * W_ih[d * 192 + j];
            ah += ps[d] * W_hh[d * 192 + j];
        }
        gx[i] = ax; gh[i] = ah;
    }
    __syncthreads();

    for (int i = t; i < 512; i += 256) {
        int s = i >> 6, dd = i & 63;
        float xr = gx[s * 192 + dd], xz = gx[s * 192 + 64 + dd], xn = gx[s * 192 + 128 + dd];
        float hr = gh[s * 192 + dd], hz = gh[s * 192 + 64 + dd], hn = gh[s * 192 + 128 + dd];
        float r_ = 1.f / (1.f + __expf(-(xr + hr)));
        float z  = 1.f / (1.f + __expf(-(xz + hz)));
        float nn = tanhf(xn + r_ * hn);
        snew[i] = (1.f - z) * nn + z * prev[i];
    }
    __syncthreads();

    {
        const float* row = snew + warp * 64;
        float x0 = row[lane], x1 = row[lane + 32];
        float s1 = x0 + x1, s2 = x0 * x0 + x1 * x1;
        #pragma unroll
        for (int o = 16; o; o >>= 1) {
            s1 += __shfl_xor_sync(0xffffffffu, s1, o);
            s2 += __shfl_xor_sync(0xffffffffu, s2, o);
        }
        float mu = s1 * 0.015625f;
        float var = s2 * 0.015625f - mu * mu;
        float rs = rsqrtf(var + LNEPS);
        sln[warp * 64 + lane]      = (x0 - mu) * rs * lnmg[lane]      + lnmb[lane];
        sln[warp * 64 + lane + 32] = (x1 - mu) * rs * lnmg[lane + 32] + lnmb[lane + 32];
    }
    __syncthreads();

    for (int i = t; i < 1024; i += 256) {
        int s = i >> 7, j = i & 127;
        float a = mb1[j];
        const float* r = sln + s * 64;
        #pragma unroll 8
        for (int d = 0; d < 64; d++) a += r[d] * mW1[d * 128 + j];
        h1[i] = fmaxf(a, 0.f);
    }
    __syncthreads();

    for (int i = t; i < 512; i += 256) {
        int s = i >> 6, c = i & 63;
        float a = mb2[c];
        const float* r = h1 + s * 128;
        #pragma unroll 8
        for (int k = 0; k < 128; k++) a += r[k] * mW2[k * 64 + c];
        float val = snew[i] + a;
        g_s[b * 512 + i] = val;
        dout[b * 512 + i] = val;
    }
}

// ---------------------------------------------------------------------------
extern "C" void kernel_launch(void* const* d_in, const int* in_sizes, int n_in,
                              void* d_out, int out_size)
{
    (void)in_sizes; (void)n_in; (void)out_size;
    const float* inputs  = (const float*)d_in[0];
    const float* slots   = (const float*)d_in[1];
    const float* ln_in_g = (const float*)d_in[2];
    const float* ln_in_b = (const float*)d_in[3];
    const float* ln_s_g  = (const float*)d_in[4];
    const float* ln_s_b  = (const float*)d_in[5];
    const float* ln_m_g  = (const float*)d_in[6];
    const float* ln_m_b  = (const float*)d_in[7];
    const float* Wq      = (const float*)d_in[8];
    const float* Wk      = (const float*)d_in[9];
    const float* Wv      = (const float*)d_in[10];
    const float* W_ih    = (const float*)d_in[11];
    const float* W_hh    = (const float*)d_in[12];
    const float* b_ih    = (const float*)d_in[13];
    const float* b_hh    = (const float*)d_in[14];
    const float* mlp_W1  = (const float*)d_in[15];
    const float* mlp_b1  = (const float*)d_in[16];
    const float* mlp_W2  = (const float*)d_in[17];
    const float* mlp_b2  = (const float*)d_in[18];
    const float* pa_W    = (const float*)d_in[19];
    const float* pa_b    = (const float*)d_in[20];
    const float* pe_g    = (const float*)d_in[21];
    const float* pe_b    = (const float*)d_in[22];
    const float* pe_W1   = (const float*)d_in[23];
    const float* pe_b1   = (const float*)d_in[24];
    const float* pe_W2   = (const float*)d_in[25];
    const float* pe_b2   = (const float*)d_in[26];
    float* out = (float*)d_out;

    static int configured = 0;
    if (!configured) {
        cudaFuncSetAttribute(preprocess_kernel,
                             cudaFuncAttributeMaxDynamicSharedMemorySize, PRE_SMEM_BYTES);
        cudaFuncSetAttribute(attn_kernel,
                             cudaFuncAttributeMaxDynamicSharedMemorySize, ATTN_SMEM_BYTES);
        configured = 1;
    }

    preprocess_kernel<<<2048, 256, PRE_SMEM_BYTES>>>(
        inputs, ln_in_g, ln_in_b, Wk, Wv, pa_W, pa_b, pe_g, pe_b,
        pe_W1, pe_b1, pe_W2, pe_b2);

    init_slots_kernel<<<32, 512>>>(slots);

    for (int it = 0; it < 3; it++) {
        slotq_kernel<<<32, 256>>>(ln_s_g, ln_s_b, Wq);
        attn_kernel<<<2048, 256, ATTN_SMEM_BYTES>>>();
        update_kernel<<<32, 256>>>(W_ih, W_hh, b_ih, b_hh,
                                   ln_m_g, ln_m_b,
                                   mlp_W1, mlp_b1, mlp_W2, mlp_b2, out);
    }
}